// round 1
// baseline (speedup 1.0000x reference)
#include <cuda_runtime.h>
#include <cuda_bf16.h>

// ============================================================================
// ECE (expected calibration error) over N=2^24 samples, 15 bins.
//   bin(c) = ceil(c*nb) - 1  for c in (0,1], else dropped
//   ece    = sum_b | sum_{i in b} (conf_i - acc_i) | / n
//
// Strategy: streaming HBM-bound pass. Per-lane PRIVATE bin accumulators in
// shared memory (layout sb[bin*TPB + tid] -> bank == lane, conflict-free,
// no atomics), float4 loads, per-block tree reduce, per-block partials to a
// __device__ scratch, tiny final kernel for sum|.|/n.
// ============================================================================

#define TPB 256
#define MAX_BINS 16          // supports num_bins <= 16 (problem uses 15)
#define NBLOCKS 1184         // 8 CTAs/SM * 148 SMs
#define MAX_BLOCKS 4096

__device__ float g_partial[MAX_BLOCKS * MAX_BINS];

__global__ __launch_bounds__(TPB)
void ece_partial_kernel(const float* __restrict__ conf,
                        const float* __restrict__ acc,
                        const int* __restrict__ num_bins_p,
                        int n) {
    __shared__ float sb[MAX_BINS * TPB];   // 16 KB, per-lane private bins
    const int tid = threadIdx.x;
    const int nb = *num_bins_p;
    const float fnb = (float)nb;

    #pragma unroll
    for (int b = 0; b < MAX_BINS; b++)
        sb[b * TPB + tid] = 0.0f;
    __syncthreads();

    const int nvec = n >> 2;
    const float4* __restrict__ c4 = (const float4*)conf;
    const float4* __restrict__ a4 = (const float4*)acc;
    const int stride = gridDim.x * blockDim.x;

    for (int i = blockIdx.x * blockDim.x + tid; i < nvec; i += stride) {
        const float4 c = __ldg(&c4[i]);
        const float4 a = __ldg(&a4[i]);
        float cv[4] = {c.x, c.y, c.z, c.w};
        float av[4] = {a.x, a.y, a.z, a.w};
        #pragma unroll
        for (int k = 0; k < 4; k++) {
            const float cf = cv[k];
            if (cf > 0.0f && cf <= 1.0f) {
                int b = (int)ceilf(cf * fnb) - 1;
                b = max(0, min(b, nb - 1));
                sb[b * TPB + tid] += cf - av[k];
            }
        }
    }

    // scalar remainder (n not multiple of 4), handled by block 0 only
    if (blockIdx.x == 0) {
        for (int i = (nvec << 2) + tid; i < n; i += blockDim.x) {
            const float cf = conf[i];
            if (cf > 0.0f && cf <= 1.0f) {
                int b = (int)ceilf(cf * fnb) - 1;
                b = max(0, min(b, nb - 1));
                sb[b * TPB + tid] += cf - acc[i];
            }
        }
    }
    __syncthreads();

    // tree-reduce over the 256 per-lane copies (conflict-free: addr stride 4B)
    for (int s = TPB / 2; s > 0; s >>= 1) {
        if (tid < s) {
            #pragma unroll
            for (int b = 0; b < MAX_BINS; b++)
                sb[b * TPB + tid] += sb[b * TPB + tid + s];
        }
        __syncthreads();
    }

    if (tid < nb)
        g_partial[blockIdx.x * MAX_BINS + tid] = sb[tid * TPB];
}

__global__ __launch_bounds__(512)
void ece_final_kernel(const int* __restrict__ num_bins_p,
                      int n, int nblocks,
                      float* __restrict__ out) {
    const int nb = *num_bins_p;
    __shared__ float bin_abs[MAX_BINS];
    const int warp = threadIdx.x >> 5;
    const int lane = threadIdx.x & 31;

    if (warp < nb) {
        float s = 0.0f;
        for (int blk = lane; blk < nblocks; blk += 32)
            s += g_partial[blk * MAX_BINS + warp];
        #pragma unroll
        for (int off = 16; off > 0; off >>= 1)
            s += __shfl_down_sync(0xffffffffu, s, off);
        if (lane == 0)
            bin_abs[warp] = fabsf(s);
    }
    __syncthreads();

    if (threadIdx.x == 0) {
        float t = 0.0f;
        for (int b = 0; b < nb; b++)
            t += bin_abs[b];
        out[0] = t / (float)n;
    }
}

extern "C" void kernel_launch(void* const* d_in, const int* in_sizes, int n_in,
                              void* d_out, int out_size) {
    const float* conf = (const float*)d_in[0];
    const float* acc  = (const float*)d_in[1];
    const int*   nbp  = (const int*)d_in[2];
    float* out = (float*)d_out;
    const int n = in_sizes[0];

    int nvec = n >> 2;
    int blocks = (nvec + TPB - 1) / TPB;
    if (blocks > NBLOCKS) blocks = NBLOCKS;
    if (blocks < 1) blocks = 1;

    ece_partial_kernel<<<blocks, TPB>>>(conf, acc, nbp, n);
    ece_final_kernel<<<1, 512>>>(nbp, n, blocks, out);
}

// round 2
// speedup vs baseline: 1.1740x; 1.1740x over previous
#include <cuda_runtime.h>
#include <cuda_bf16.h>

// ============================================================================
// ECE over N=2^24 samples, 15 bins — single fused kernel.
//   bin(c) = ceil(c*nb) - 1  for c in (0,1], else dropped
//   ece    = sum_b | sum_{i in b} (conf_i - acc_i) | / n
//
// Streaming HBM-bound pass with per-lane PRIVATE bin accumulators in shared
// memory (sb[bin*256 + tid] -> bank == lane, conflict-free, no atomics),
// 4x-unrolled float4 loads (8 front-batched LDG.128), per-block tree reduce,
// then a threadfence+ticket "last block" tail reduction (no 2nd launch).
// ============================================================================

#define TPB 256
#define MAX_BINS 16          // supports num_bins <= 16 (problem uses 15)
#define NBLOCKS 1024         // 2^18 threads: divides nvec=2^22 exactly
#define MAX_BLOCKS 4096

__device__ float g_partial[MAX_BLOCKS * MAX_BINS];
__device__ unsigned int g_count = 0;

__device__ __forceinline__ void bin_add(float* __restrict__ sb, int tid,
                                        float cf, float af, float fnb, int nbm1) {
    if (cf > 0.0f && cf <= 1.0f) {
        int b = __float2int_ru(cf * fnb) - 1;   // ceil(c*nb)-1, single F2I.CEIL
        b = max(0, min(b, nbm1));
        sb[b * TPB + tid] += cf - af;
    }
}

__global__ __launch_bounds__(TPB, 8)
void ece_kernel(const float* __restrict__ conf,
                const float* __restrict__ acc,
                const int* __restrict__ num_bins_p,
                int n,
                float* __restrict__ out) {
    __shared__ float sb[MAX_BINS * TPB];   // 16 KB, per-lane private bins
    const int tid = threadIdx.x;
    const int nb = *num_bins_p;
    const float fnb = (float)nb;
    const int nbm1 = nb - 1;

    #pragma unroll
    for (int b = 0; b < MAX_BINS; b++)
        sb[b * TPB + tid] = 0.0f;
    __syncthreads();

    const int nvec = n >> 2;
    const float4* __restrict__ c4 = (const float4*)conf;
    const float4* __restrict__ a4 = (const float4*)acc;
    const int T = gridDim.x * blockDim.x;

    int i = blockIdx.x * blockDim.x + tid;
    // 4x unrolled grid-stride: 8 front-batched LDG.128 per iteration
    for (; i + 3 * T < nvec; i += 4 * T) {
        const float4 c0 = __ldg(&c4[i]);
        const float4 c1 = __ldg(&c4[i + T]);
        const float4 c2 = __ldg(&c4[i + 2 * T]);
        const float4 c3 = __ldg(&c4[i + 3 * T]);
        const float4 a0 = __ldg(&a4[i]);
        const float4 a1 = __ldg(&a4[i + T]);
        const float4 a2 = __ldg(&a4[i + 2 * T]);
        const float4 a3 = __ldg(&a4[i + 3 * T]);
        bin_add(sb, tid, c0.x, a0.x, fnb, nbm1);
        bin_add(sb, tid, c0.y, a0.y, fnb, nbm1);
        bin_add(sb, tid, c0.z, a0.z, fnb, nbm1);
        bin_add(sb, tid, c0.w, a0.w, fnb, nbm1);
        bin_add(sb, tid, c1.x, a1.x, fnb, nbm1);
        bin_add(sb, tid, c1.y, a1.y, fnb, nbm1);
        bin_add(sb, tid, c1.z, a1.z, fnb, nbm1);
        bin_add(sb, tid, c1.w, a1.w, fnb, nbm1);
        bin_add(sb, tid, c2.x, a2.x, fnb, nbm1);
        bin_add(sb, tid, c2.y, a2.y, fnb, nbm1);
        bin_add(sb, tid, c2.z, a2.z, fnb, nbm1);
        bin_add(sb, tid, c2.w, a2.w, fnb, nbm1);
        bin_add(sb, tid, c3.x, a3.x, fnb, nbm1);
        bin_add(sb, tid, c3.y, a3.y, fnb, nbm1);
        bin_add(sb, tid, c3.z, a3.z, fnb, nbm1);
        bin_add(sb, tid, c3.w, a3.w, fnb, nbm1);
    }
    for (; i < nvec; i += T) {
        const float4 c = __ldg(&c4[i]);
        const float4 a = __ldg(&a4[i]);
        bin_add(sb, tid, c.x, a.x, fnb, nbm1);
        bin_add(sb, tid, c.y, a.y, fnb, nbm1);
        bin_add(sb, tid, c.z, a.z, fnb, nbm1);
        bin_add(sb, tid, c.w, a.w, fnb, nbm1);
    }
    // scalar remainder (n not multiple of 4): block 0 only
    if (blockIdx.x == 0) {
        for (int j = (nvec << 2) + tid; j < n; j += blockDim.x) {
            const float cf = conf[j];
            if (cf > 0.0f && cf <= 1.0f) {
                int b = __float2int_ru(cf * fnb) - 1;
                b = max(0, min(b, nbm1));
                sb[b * TPB + tid] += cf - acc[j];
            }
        }
    }
    __syncthreads();

    // tree-reduce the 256 per-lane copies (addr stride 4B -> conflict-free)
    for (int s = TPB / 2; s > 0; s >>= 1) {
        if (tid < s) {
            #pragma unroll
            for (int b = 0; b < MAX_BINS; b++)
                sb[b * TPB + tid] += sb[b * TPB + tid + s];
        }
        __syncthreads();
    }

    if (tid < MAX_BINS)
        g_partial[blockIdx.x * MAX_BINS + tid] = sb[tid * TPB];

    // ---- last-block tail reduction (no second launch) ----
    __shared__ bool is_last;
    __threadfence();
    if (tid == 0) {
        unsigned int ticket = atomicAdd(&g_count, 1u);
        is_last = (ticket == gridDim.x - 1);
    }
    __syncthreads();

    if (is_last) {
        __threadfence();
        // total = gridDim.x * 16; element e -> bin (e & 15). Stride 256 keeps
        // bin = tid & 15 constant per thread; loads fully coalesced+independent.
        const int total = gridDim.x * MAX_BINS;
        float s = 0.0f;
        for (int e = tid; e < total; e += TPB)
            s += g_partial[e];

        __shared__ float red[TPB];
        red[tid] = s;
        __syncthreads();

        if (tid < MAX_BINS) {
            float t = 0.0f;
            #pragma unroll
            for (int k = 0; k < TPB / MAX_BINS; k++)
                t += red[tid + k * MAX_BINS];
            red[tid] = fabsf(t);     // bins >= nb hold exact zeros
        }
        __syncthreads();

        if (tid == 0) {
            float tot = 0.0f;
            #pragma unroll
            for (int b = 0; b < MAX_BINS; b++)
                tot += red[b];
            out[0] = tot / (float)n;
            g_count = 0;             // reset for next graph replay
        }
    }
}

extern "C" void kernel_launch(void* const* d_in, const int* in_sizes, int n_in,
                              void* d_out, int out_size) {
    const float* conf = (const float*)d_in[0];
    const float* acc  = (const float*)d_in[1];
    const int*   nbp  = (const int*)d_in[2];
    float* out = (float*)d_out;
    const int n = in_sizes[0];

    int nvec = n >> 2;
    int blocks = (nvec + TPB - 1) / TPB;
    if (blocks > NBLOCKS) blocks = NBLOCKS;
    if (blocks < 1) blocks = 1;

    ece_kernel<<<blocks, TPB>>>(conf, acc, nbp, n, out);
}